// round 7
// baseline (speedup 1.0000x reference)
#include <cuda_runtime.h>

#define NS   16
#define NP   2048
#define DIMS 64
#define KK   16
#define BLK  64      // threads per block; each thread owns 2 queries
#define TJ   64      // candidate tile size
#define HALF 1024    // candidates per half
#define TOT  (NS*NP*KK)

typedef unsigned long long u64;
typedef unsigned int       u32;

__device__ float g_x2[NS * NP];
__device__ u64   g_part[2 * NS * NP * KK];   // (ordered-dist<<32 | idx) partial top-K

// ---------- row squared norms ----------
__global__ void x2_kernel(const float* __restrict__ h) {
    int r = blockIdx.x * blockDim.x + threadIdx.x;
    if (r >= NS * NP) return;
    const float4* p = (const float4*)(h + (size_t)r * DIMS);
    float s = 0.f;
#pragma unroll
    for (int t = 0; t < DIMS / 4; t++) {
        float4 v = p[t];
        s += v.x * v.x + v.y * v.y + v.z * v.z + v.w * v.w;
    }
    g_x2[r] = s;
}

// ---------- packed f32x2 helpers ----------
__device__ __forceinline__ u64 pack2(float x) {
    u64 r;
    asm("mov.b64 %0, {%1, %1};" : "=l"(r) : "f"(x));
    return r;
}
__device__ __forceinline__ void ffma2(u64& d, u64 a, u64 b) {
    asm("fma.rn.f32x2 %0, %1, %2, %0;" : "+l"(d) : "l"(a), "l"(b));
}
__device__ __forceinline__ float2 unpack2(u64 v) {
    float2 f;
    asm("mov.b64 {%0, %1}, %2;" : "=f"(f.x), "=f"(f.y) : "l"(v));
    return f;
}

// ---------- order-preserving float->uint (handles negatives) ----------
__device__ __forceinline__ u32 fkey(float f) {
    u32 u = __float_as_uint(f);
    return u ^ (u32)(((int)u >> 31) | 0x80000000);
}
__device__ __forceinline__ float funkey(u32 k) {
    u32 u = (k & 0x80000000u) ? (k ^ 0x80000000u) : ~k;
    return __uint_as_float(u);
}

// ---------- sorted register top-K on u64 keys (exact, stable) ----------
__device__ __forceinline__ void topk_insert(u64 (&kd)[KK], u64 v) {
    kd[KK - 1] = v;
#pragma unroll
    for (int t = KK - 1; t > 0; t--) {
        if (kd[t] < kd[t - 1]) {
            u64 tmp = kd[t]; kd[t] = kd[t - 1]; kd[t - 1] = tmp;
        }
    }
}

__global__ __launch_bounds__(BLK) void knn_kernel(const float* __restrict__ h) {
    __shared__ float sh[DIMS][TJ];   // transposed candidate tile: sh[d][j]
    __shared__ float shx2[TJ];

    const int qt   = blockIdx.x;     // query tile (128 queries)
    const int b    = blockIdx.y;     // sample
    const int half = blockIdx.z;     // candidate half
    const int tid  = threadIdx.x;
    const int ia   = qt * 128 + tid;        // query A
    const int ib   = ia + 64;               // query B

    // both query vectors in registers
    float qa[DIMS], qb[DIMS];
    {
        const float4* pa = (const float4*)(h + ((size_t)b * NP + ia) * DIMS);
        const float4* pb = (const float4*)(h + ((size_t)b * NP + ib) * DIMS);
#pragma unroll
        for (int t = 0; t < DIMS / 4; t++) {
            float4 va = pa[t];
            qa[4 * t + 0] = va.x; qa[4 * t + 1] = va.y;
            qa[4 * t + 2] = va.z; qa[4 * t + 3] = va.w;
            float4 vb = pb[t];
            qb[4 * t + 0] = vb.x; qb[4 * t + 1] = vb.y;
            qb[4 * t + 2] = vb.z; qb[4 * t + 3] = vb.w;
        }
    }
    const float qx2a = g_x2[b * NP + ia];
    const float qx2b = g_x2[b * NP + ib];

    u64 kda[KK], kdb[KK];
#pragma unroll
    for (int k = 0; k < KK; k++) {
        kda[k] = ~0ull;
        kdb[k] = ~0ull;
    }

    const int jbeg = half * HALF;

#pragma unroll 1
    for (int j0 = jbeg; j0 < jbeg + HALF; j0 += TJ) {
        __syncthreads();
        // stage TJ candidate rows, transposed
        {
            const float4* hr =
                (const float4*)(h + ((size_t)b * NP + j0 + tid) * DIMS);
#pragma unroll
            for (int t = 0; t < DIMS / 4; t++) {
                float4 v = hr[t];
                sh[4 * t + 0][tid] = v.x;
                sh[4 * t + 1][tid] = v.y;
                sh[4 * t + 2][tid] = v.z;
                sh[4 * t + 3][tid] = v.w;
            }
            shx2[tid] = g_x2[b * NP + j0 + tid];
        }
        __syncthreads();

#pragma unroll 1
        for (int js = 0; js < TJ; js += 16) {
            u64 acca[8], accb[8];
#pragma unroll
            for (int p = 0; p < 8; p++) { acca[p] = 0ull; accb[p] = 0ull; }

#pragma unroll
            for (int d = 0; d < DIMS; d++) {
                u64 q2a = pack2(qa[d]);
                u64 q2b = pack2(qb[d]);
                const ulonglong2* srow = (const ulonglong2*)&sh[d][js];
#pragma unroll
                for (int p = 0; p < 4; p++) {
                    ulonglong2 sv = srow[p];   // one 16B load feeds 4 FFMA2
                    ffma2(acca[2 * p + 0], q2a, sv.x);
                    ffma2(acca[2 * p + 1], q2a, sv.y);
                    ffma2(accb[2 * p + 0], q2b, sv.x);
                    ffma2(accb[2 * p + 1], q2b, sv.y);
                }
            }

#pragma unroll
            for (int p = 0; p < 8; p++) {
                float2 da = unpack2(acca[p]);
                float2 db = unpack2(accb[p]);
                u32    j  = (u32)(j0 + js + 2 * p);
                float  s0 = shx2[js + 2 * p + 0];
                float  s1 = shx2[js + 2 * p + 1];
                float a0 = fmaf(-2.f, da.x, qx2a + s0);
                float a1 = fmaf(-2.f, da.y, qx2a + s1);
                float b0 = fmaf(-2.f, db.x, qx2b + s0);
                float b1 = fmaf(-2.f, db.y, qx2b + s1);
                u64 ka0 = ((u64)fkey(a0) << 32) | j;
                u64 ka1 = ((u64)fkey(a1) << 32) | (j + 1);
                u64 kb0 = ((u64)fkey(b0) << 32) | j;
                u64 kb1 = ((u64)fkey(b1) << 32) | (j + 1);
                if (ka0 < kda[KK - 1]) topk_insert(kda, ka0);
                if (ka1 < kda[KK - 1]) topk_insert(kda, ka1);
                if (kb0 < kdb[KK - 1]) topk_insert(kdb, kb0);
                if (kb1 < kdb[KK - 1]) topk_insert(kdb, kb1);
            }
        }
    }

    // write partial top-K (sorted ascending)
    u64* pouta = g_part + (size_t)half * (NS * NP * KK)
               + ((size_t)b * NP + ia) * KK;
    u64* poutb = g_part + (size_t)half * (NS * NP * KK)
               + ((size_t)b * NP + ib) * KK;
#pragma unroll
    for (int k = 0; k < KK; k++) { pouta[k] = kda[k]; poutb[k] = kdb[k]; }
}

// ---------- merge the two sorted per-half top-K lists ----------
__global__ void merge_kernel(float* __restrict__ out) {
    int q = blockIdx.x * blockDim.x + threadIdx.x;
    if (q >= NS * NP) return;
    int b = q / NP;
    int i = q % NP;

    const u64* A = g_part + (size_t)q * KK;
    const u64* B = g_part + (size_t)(NS * NP * KK) + (size_t)q * KK;

    const size_t base = (size_t)q * KK;
    const float  goff = (float)(b * NP);
    const float  srcv = (float)(i) + goff;

    int pa = 0, pb = 0;
#pragma unroll
    for (int k = 0; k < KK; k++) {
        u64 va = (pa < KK) ? A[pa] : ~0ull;
        u64 vb = (pb < KK) ? B[pb] : ~0ull;
        u64 v;
        if (va <= vb) { v = va; pa++; } else { v = vb; pb++; }
        float dst = funkey((u32)(v >> 32));
        int   idx = (int)(u32)(v & 0xffffffffu);
        out[base + k]                   = dst;
        out[(size_t)TOT + base + k]     = (float)idx + goff;
        out[2 * (size_t)TOT + base + k] = srcv;
    }
}

extern "C" void kernel_launch(void* const* d_in, const int* in_sizes, int n_in,
                              void* d_out, int out_size) {
    const float* h = (const float*)d_in[0];
    (void)in_sizes; (void)n_in; (void)out_size;

    x2_kernel<<<(NS * NP + 255) / 256, 256>>>(h);

    dim3 grid(NP / 128, NS, 2);   // 16 query tiles x 16 samples x 2 halves
    knn_kernel<<<grid, BLK>>>(h);

    merge_kernel<<<(NS * NP + 127) / 128, 128>>>((float*)d_out);
}

// round 8
// speedup vs baseline: 1.3287x; 1.3287x over previous
#include <cuda_runtime.h>

#define NS   16
#define NP   2048
#define DIMS 64
#define KK   16
#define BLK  128     // threads per block == queries per block
#define TJ   128     // candidate tile size
#define QS   4       // candidate-range splits
#define SPAN (NP/QS) // candidates per split (512)
#define TOT  (NS*NP*KK)

typedef unsigned long long u64;
typedef unsigned int       u32;

__device__ float g_x2[NS * NP];
__device__ u64   g_part[QS * NS * NP * KK];   // sorted partial top-K per split

// ---------- row squared norms ----------
__global__ void x2_kernel(const float* __restrict__ h) {
    int r = blockIdx.x * blockDim.x + threadIdx.x;
    if (r >= NS * NP) return;
    const float4* p = (const float4*)(h + (size_t)r * DIMS);
    float s = 0.f;
#pragma unroll
    for (int t = 0; t < DIMS / 4; t++) {
        float4 v = p[t];
        s += v.x * v.x + v.y * v.y + v.z * v.z + v.w * v.w;
    }
    g_x2[r] = s;
}

// ---------- packed f32x2 helpers ----------
__device__ __forceinline__ u64 pack2(float x) {
    u64 r;
    asm("mov.b64 %0, {%1, %1};" : "=l"(r) : "f"(x));
    return r;
}
__device__ __forceinline__ void ffma2(u64& d, u64 a, u64 b) {
    asm("fma.rn.f32x2 %0, %1, %2, %0;" : "+l"(d) : "l"(a), "l"(b));
}
__device__ __forceinline__ float2 unpack2(u64 v) {
    float2 f;
    asm("mov.b64 {%0, %1}, %2;" : "=f"(f.x), "=f"(f.y) : "l"(v));
    return f;
}

// ---------- order-preserving float<->uint ----------
__device__ __forceinline__ u32 fkey(float f) {
    u32 u = __float_as_uint(f);
    return u ^ (u32)(((int)u >> 31) | 0x80000000);
}
__device__ __forceinline__ float funkey(u32 k) {
    u32 u = (k & 0x80000000u) ? (k ^ 0x80000000u) : ~k;
    return __uint_as_float(u);
}

// ---------- sorted register top-K (stable, strict <) ----------
__device__ __forceinline__ void topk_insert(float (&kd)[KK], int (&ki)[KK],
                                            float d, int j) {
    kd[KK - 1] = d;
    ki[KK - 1] = j;
#pragma unroll
    for (int t = KK - 1; t > 0; t--) {
        if (kd[t] < kd[t - 1]) {
            float td = kd[t]; kd[t] = kd[t - 1]; kd[t - 1] = td;
            int   ti = ki[t]; ki[t] = ki[t - 1]; ki[t - 1] = ti;
        }
    }
}

__global__ __launch_bounds__(BLK) void knn_kernel(const float* __restrict__ h) {
    __shared__ float sh[DIMS][TJ];   // transposed candidate tile: sh[d][j]
    __shared__ float shx2[TJ];

    const int b   = blockIdx.y;
    const int z   = blockIdx.z;      // candidate quarter
    const int tid = threadIdx.x;
    const int i   = blockIdx.x * BLK + tid;

    // query vector in registers
    float q[DIMS];
    {
        const float4* hq = (const float4*)(h + ((size_t)b * NP + i) * DIMS);
#pragma unroll
        for (int t = 0; t < DIMS / 4; t++) {
            float4 v = hq[t];
            q[4 * t + 0] = v.x; q[4 * t + 1] = v.y;
            q[4 * t + 2] = v.z; q[4 * t + 3] = v.w;
        }
    }
    const float qx2 = g_x2[b * NP + i];

    float kd[KK];
    int   ki[KK];
#pragma unroll
    for (int k = 0; k < KK; k++) { kd[k] = __int_as_float(0x7f800000); ki[k] = 0; }

    const int jbeg = z * SPAN;

#pragma unroll 1
    for (int j0 = jbeg; j0 < jbeg + SPAN; j0 += TJ) {
        __syncthreads();
        // cooperatively stage TJ candidate rows, transposed
        {
            const float4* hr =
                (const float4*)(h + ((size_t)b * NP + j0 + tid) * DIMS);
#pragma unroll
            for (int t = 0; t < DIMS / 4; t++) {
                float4 v = hr[t];
                sh[4 * t + 0][tid] = v.x;
                sh[4 * t + 1][tid] = v.y;
                sh[4 * t + 2][tid] = v.z;
                sh[4 * t + 3][tid] = v.w;
            }
            shx2[tid] = g_x2[b * NP + j0 + tid];
        }
        __syncthreads();

#pragma unroll 1
        for (int js = 0; js < TJ; js += 16) {
            u64 acc[8];
#pragma unroll
            for (int p = 0; p < 8; p++) acc[p] = 0ull;

#pragma unroll
            for (int d = 0; d < DIMS; d++) {
                u64 q2 = pack2(q[d]);
                const ulonglong2* srow = (const ulonglong2*)&sh[d][js];
#pragma unroll
                for (int p = 0; p < 4; p++) {
                    ulonglong2 sv = srow[p];   // broadcast LDS.128
                    ffma2(acc[2 * p + 0], q2, sv.x);
                    ffma2(acc[2 * p + 1], q2, sv.y);
                }
            }

#pragma unroll
            for (int p = 0; p < 8; p++) {
                float2 dot = unpack2(acc[p]);
                int    j   = j0 + js + 2 * p;
                float  d0  = fmaf(-2.f, dot.x, qx2 + shx2[js + 2 * p + 0]);
                float  d1  = fmaf(-2.f, dot.y, qx2 + shx2[js + 2 * p + 1]);
                if (d0 < kd[KK - 1]) topk_insert(kd, ki, d0, j);
                if (d1 < kd[KK - 1]) topk_insert(kd, ki, d1, j + 1);
            }
        }
    }

    // write sorted partial as lossless u64 keys
    u64* pout = g_part + ((size_t)z * (NS * NP) + (size_t)b * NP + i) * KK;
#pragma unroll
    for (int k = 0; k < KK; k++)
        pout[k] = ((u64)fkey(kd[k]) << 32) | (u32)ki[k];
}

// ---------- 4-way merge of sorted per-split top-K lists ----------
__global__ void merge_kernel(float* __restrict__ out) {
    int q = blockIdx.x * blockDim.x + threadIdx.x;
    if (q >= NS * NP) return;
    int b = q / NP;
    int i = q % NP;

    const u64* L[QS];
#pragma unroll
    for (int l = 0; l < QS; l++)
        L[l] = g_part + ((size_t)l * (NS * NP) + q) * KK;

    u64 head[QS];
    int ptr[QS];
#pragma unroll
    for (int l = 0; l < QS; l++) { head[l] = L[l][0]; ptr[l] = 0; }

    const size_t base = (size_t)q * KK;
    const float  goff = (float)(b * NP);
    const float  srcv = (float)(i) + goff;

#pragma unroll
    for (int k = 0; k < KK; k++) {
        int best = 0;
#pragma unroll
        for (int l = 1; l < QS; l++)
            if (head[l] < head[best]) best = l;
        u64 v = head[best];
        ptr[best]++;
        head[best] = (ptr[best] < KK) ? L[best][ptr[best]] : ~0ull;

        float dst = funkey((u32)(v >> 32));
        int   idx = (int)(u32)(v & 0xffffffffu);
        out[base + k]                   = dst;
        out[(size_t)TOT + base + k]     = (float)idx + goff;
        out[2 * (size_t)TOT + base + k] = srcv;
    }
}

extern "C" void kernel_launch(void* const* d_in, const int* in_sizes, int n_in,
                              void* d_out, int out_size) {
    const float* h = (const float*)d_in[0];
    (void)in_sizes; (void)n_in; (void)out_size;

    x2_kernel<<<(NS * NP + 255) / 256, 256>>>(h);

    dim3 grid(NP / BLK, NS, QS);   // 16 x 16 x 4 = 1024 blocks
    knn_kernel<<<grid, BLK>>>(h);

    merge_kernel<<<(NS * NP + 127) / 128, 128>>>((float*)d_out);
}